// round 14
// baseline (speedup 1.0000x reference)
#include <cuda_runtime.h>
#include <cuda_bf16.h>
#include <stdint.h>

// ============================================================================
// GumbelTopK R14: R13 fused structure + 16-bit key store.
//  reset:    zero hist1 + counters (1 block, tiny)
//  A:        score -> key16 (32MB W) + 12-bit smem hist; also zeros
//            hist2 slices (blocks finish before finalcand)       [160MB]
//  select1:  12-bit bin holding rank k
//  finalcand: key16 (32MB) + u2 (128MB) -> out (64MB); in-bin
//            (~2.7%) gathers logits/u1, recomputes exact key32,
//            feeds 20-bit hist + candidate list                  [~255MB]
//  select2/ties/cutoff: exact threshold T, rank r, index cutoff
//  fixup2:   rewrite included candidates with exact gumbel       [small]
// m=1 gumbel: a1 < e*a0 (R12/R13-validated exact); m=0: u1 > u0.
// ============================================================================

#define N_MAX    (1u << 24)      // 4096*4096
#define H1_BINS  4096
#define H2_BINS  (1u << 20)
#define CAND_CAP (1u << 22)
#define TIE_CAP  (1u << 20)
#define CCAP     2048
#define EPSF     1e-8f
#define EULER_F  2.7182818284590452f

__device__ unsigned short g_key16[N_MAX];
__device__ unsigned int   g_cand_key[CAND_CAP];
__device__ int            g_cand_idx[CAND_CAP];
__device__ int            g_tie_idx[TIE_CAP];
__device__ unsigned int   g_hist1[H1_BINS];
__device__ unsigned int   g_hist2[H2_BINS];
__device__ unsigned int   g_csum2[1024];
__device__ unsigned int   g_cand_cnt;
__device__ unsigned int   g_tie_cnt;
__device__ unsigned int   g_prefix12;
__device__ unsigned int   g_k1;
__device__ unsigned int   g_T;
__device__ unsigned int   g_r;
__device__ int            g_cutoff;

__device__ __forceinline__ float gum(float u) {
    return -logf(-logf(u + EPSF) + EPSF);
}

__device__ __forceinline__ unsigned int f2key(float f) {
    unsigned int b = __float_as_uint(f);
    return (b & 0x80000000u) ? ~b : (b | 0x80000000u);
}

// ---------------------------------------------------------------------------
// reset: hist1 + counters only (hist2 zeroed inside score16_k).
// ---------------------------------------------------------------------------
__global__ void reset_k() {
    for (int i = threadIdx.x; i < H1_BINS; i += blockDim.x) g_hist1[i] = 0;
    if (threadIdx.x == 0) { g_cand_cnt = 0; g_tie_cnt = 0; }
}

// ---------------------------------------------------------------------------
// pass A: score -> key16 store + 12-bit smem histogram (2-way replicated).
// Each block also zeros its slice of g_hist2 (safe: finalcand is a later
// kernel, so all zeroing completes before any hist2 atomic).
// Launch with EXACTLY 2048 blocks x 256 threads.
// ---------------------------------------------------------------------------
__global__ void __launch_bounds__(256) score16_k(
        const float* __restrict__ logits,
        const float* __restrict__ u1,
        const int* __restrict__ training, int n4) {
    // zero hist2 slice: 1M bins / 2048 blocks = 512 each
    {
        unsigned int base = blockIdx.x * (H2_BINS / 2048);
        for (int j = threadIdx.x; j < H2_BINS / 2048; j += blockDim.x)
            g_hist2[base + j] = 0;
    }
    __shared__ unsigned int sh[2 * H1_BINS];     // 32 KB
    for (int i = threadIdx.x; i < 2 * H1_BINS; i += blockDim.x) sh[i] = 0;
    __syncthreads();
    unsigned int* mysh = sh + ((threadIdx.x >> 5) & 1) * H1_BINS;
    const int tr = *training;
    const int stride = gridDim.x * blockDim.x;
    int i = blockIdx.x * blockDim.x + threadIdx.x;
    for (; i + stride < n4; i += 2 * stride) {
        float4 l0 = __ldcs((const float4*)logits + i);
        float4 u0 = __ldcs((const float4*)u1 + i);
        float4 l1 = __ldcs((const float4*)logits + i + stride);
        float4 u1v = __ldcs((const float4*)u1 + i + stride);
        unsigned int a0 = f2key(tr ? (l0.x + gum(u0.x)) : l0.x);
        unsigned int a1 = f2key(tr ? (l0.y + gum(u0.y)) : l0.y);
        unsigned int a2 = f2key(tr ? (l0.z + gum(u0.z)) : l0.z);
        unsigned int a3 = f2key(tr ? (l0.w + gum(u0.w)) : l0.w);
        unsigned int b0 = f2key(tr ? (l1.x + gum(u1v.x)) : l1.x);
        unsigned int b1 = f2key(tr ? (l1.y + gum(u1v.y)) : l1.y);
        unsigned int b2 = f2key(tr ? (l1.z + gum(u1v.z)) : l1.z);
        unsigned int b3 = f2key(tr ? (l1.w + gum(u1v.w)) : l1.w);
        uint2 p0, p1;
        p0.x = (a0 >> 16) | (a1 & 0xFFFF0000u);
        p0.y = (a2 >> 16) | (a3 & 0xFFFF0000u);
        p1.x = (b0 >> 16) | (b1 & 0xFFFF0000u);
        p1.y = (b2 >> 16) | (b3 & 0xFFFF0000u);
        ((uint2*)g_key16)[i] = p0;
        ((uint2*)g_key16)[i + stride] = p1;
        atomicAdd(&mysh[a0 >> 20], 1u);
        atomicAdd(&mysh[a1 >> 20], 1u);
        atomicAdd(&mysh[a2 >> 20], 1u);
        atomicAdd(&mysh[a3 >> 20], 1u);
        atomicAdd(&mysh[b0 >> 20], 1u);
        atomicAdd(&mysh[b1 >> 20], 1u);
        atomicAdd(&mysh[b2 >> 20], 1u);
        atomicAdd(&mysh[b3 >> 20], 1u);
    }
    for (; i < n4; i += stride) {
        float4 l = __ldcs((const float4*)logits + i);
        float4 u = __ldcs((const float4*)u1 + i);
        unsigned int a0 = f2key(tr ? (l.x + gum(u.x)) : l.x);
        unsigned int a1 = f2key(tr ? (l.y + gum(u.y)) : l.y);
        unsigned int a2 = f2key(tr ? (l.z + gum(u.z)) : l.z);
        unsigned int a3 = f2key(tr ? (l.w + gum(u.w)) : l.w);
        uint2 p;
        p.x = (a0 >> 16) | (a1 & 0xFFFF0000u);
        p.y = (a2 >> 16) | (a3 & 0xFFFF0000u);
        ((uint2*)g_key16)[i] = p;
        atomicAdd(&mysh[a0 >> 20], 1u);
        atomicAdd(&mysh[a1 >> 20], 1u);
        atomicAdd(&mysh[a2 >> 20], 1u);
        atomicAdd(&mysh[a3 >> 20], 1u);
    }
    __syncthreads();
    for (int b = threadIdx.x; b < H1_BINS; b += blockDim.x) {
        unsigned int c = sh[b] + sh[b + H1_BINS];
        if (c) atomicAdd(&g_hist1[b], c);
    }
}

// ---------------------------------------------------------------------------
__device__ __forceinline__ unsigned int block_incl_scan(unsigned int v, unsigned int* sh) {
    int t = threadIdx.x;
    sh[t] = v;
    __syncthreads();
    for (int off = 1; off < blockDim.x; off <<= 1) {
        unsigned int add = (t >= off) ? sh[t - off] : 0u;
        __syncthreads();
        sh[t] += add;
        __syncthreads();
    }
    return sh[t];
}

// select level 1: 12-bit bin holding rank-k (descending)
__global__ void select1_k(const int* __restrict__ kp) {
    __shared__ unsigned int sh[1024];
    const unsigned int k = (unsigned int)(*kp);
    int t = threadIdx.x;
    unsigned int c[4], s = 0;
#pragma unroll
    for (int j = 0; j < 4; j++) { c[j] = g_hist1[4095 - (4 * t + j)]; s += c[j]; }
    unsigned int incl = block_incl_scan(s, sh);
    unsigned int excl = incl - s;
    if (excl < k && k <= incl) {
        unsigned int cum = excl;
#pragma unroll
        for (int j = 0; j < 4; j++) {
            if (cum + c[j] >= k) { g_prefix12 = 4095 - (4 * t + j); g_k1 = k - cum; break; }
            cum += c[j];
        }
    }
}

// ---------------------------------------------------------------------------
// finalcand: fused output + in-bin resolve.
// Streams key16 (8/thread-iter) + u2 -> out. top12 > pfx -> mask 1;
// < pfx -> mask 0; == pfx -> gather logits/u1, recompute exact key32,
// hist2 atomic + staged candidate, provisional 0.
// ---------------------------------------------------------------------------
__device__ __forceinline__ float fc_elem(
        unsigned int key16, int idx, float v0, float v1,
        const float* __restrict__ logits, const float* __restrict__ u1,
        unsigned int pfx, int tr,
        uint2* s_buf, int* s_cnt) {
    unsigned int top = key16 >> 4;
    unsigned int m = (top > pfx) ? 1u : 0u;
    if (top == pfx) {
        float l = __ldg(&logits[idx]);
        float u = __ldg(&u1[idx]);
        unsigned int key = f2key(tr ? (l + gum(u)) : l);
        atomicAdd(&g_hist2[key & 0xFFFFFu], 1u);
        int q = atomicAdd(s_cnt, 1);
        if (q < CCAP) s_buf[q] = make_uint2(key, (unsigned int)idx);
    }
    if (!tr) return m ? 1.0f : 0.0f;
    if (m) {
        float a0 = -logf(v0 + EPSF) + EPSF;
        float a1 = -logf(v1 + EPSF) + EPSF;
        return (a1 < EULER_F * a0) ? 1.0f : 0.0f;
    }
    return (v1 > v0) ? 1.0f : 0.0f;
}

__global__ void __launch_bounds__(256) finalcand_k(
        const float* __restrict__ u2,
        const float* __restrict__ logits,
        const float* __restrict__ u1,
        const int* __restrict__ training,
        float* __restrict__ out, int n8) {
    __shared__ uint2 s_buf[CCAP];    // 16 KB
    __shared__ int s_cnt;
    __shared__ unsigned int s_base;
    if (threadIdx.x == 0) s_cnt = 0;
    __syncthreads();
    const unsigned int pfx = g_prefix12;
    const int tr = *training;
    const int stride = gridDim.x * blockDim.x;
    for (int i = blockIdx.x * blockDim.x + threadIdx.x; i < n8; i += stride) {
        uint4 pk = __ldcs((const uint4*)g_key16 + i);      // 8 key16s
        float4 ua = __ldcs((const float4*)u2 + 4 * i + 0);
        float4 ub = __ldcs((const float4*)u2 + 4 * i + 1);
        float4 uc = __ldcs((const float4*)u2 + 4 * i + 2);
        float4 ud = __ldcs((const float4*)u2 + 4 * i + 3);
        int e = 8 * i;
        float4 o0, o1;
        o0.x = fc_elem(pk.x & 0xFFFFu, e + 0, ua.x, ua.y, logits, u1, pfx, tr, s_buf, &s_cnt);
        o0.y = fc_elem(pk.x >> 16,     e + 1, ua.z, ua.w, logits, u1, pfx, tr, s_buf, &s_cnt);
        o0.z = fc_elem(pk.y & 0xFFFFu, e + 2, ub.x, ub.y, logits, u1, pfx, tr, s_buf, &s_cnt);
        o0.w = fc_elem(pk.y >> 16,     e + 3, ub.z, ub.w, logits, u1, pfx, tr, s_buf, &s_cnt);
        o1.x = fc_elem(pk.z & 0xFFFFu, e + 4, uc.x, uc.y, logits, u1, pfx, tr, s_buf, &s_cnt);
        o1.y = fc_elem(pk.z >> 16,     e + 5, uc.z, uc.w, logits, u1, pfx, tr, s_buf, &s_cnt);
        o1.z = fc_elem(pk.w & 0xFFFFu, e + 6, ud.x, ud.y, logits, u1, pfx, tr, s_buf, &s_cnt);
        o1.w = fc_elem(pk.w >> 16,     e + 7, ud.z, ud.w, logits, u1, pfx, tr, s_buf, &s_cnt);
        __stcs((float4*)out + 2 * i, o0);
        __stcs((float4*)out + 2 * i + 1, o1);
    }
    __syncthreads();
    int cnt = s_cnt;
    if (cnt > CCAP) cnt = CCAP;
    if (threadIdx.x == 0) s_base = atomicAdd(&g_cand_cnt, (unsigned int)cnt);
    __syncthreads();
    unsigned int base = s_base;
    for (int t = threadIdx.x; t < cnt; t += blockDim.x) {
        unsigned int p = base + t;
        if (p < CAND_CAP) {
            g_cand_key[p] = s_buf[t].x;
            g_cand_idx[p] = (int)s_buf[t].y;
        }
    }
}

// chunk sums of hist2 (1024 chunks of 1024 bins)
__global__ void chunksum2_k() {
    __shared__ unsigned int sh[256];
    int b = blockIdx.x;
    unsigned int s = 0;
    for (int j = threadIdx.x; j < 1024; j += 256) s += g_hist2[b * 1024 + j];
    sh[threadIdx.x] = s;
    __syncthreads();
    for (int off = 128; off > 0; off >>= 1) {
        if (threadIdx.x < off) sh[threadIdx.x] += sh[threadIdx.x + off];
        __syncthreads();
    }
    if (threadIdx.x == 0) g_csum2[b] = sh[0];
}

// select level 2: exact threshold key T and r = #(==T) to include
__global__ void select2_k() {
    __shared__ unsigned int sh[1024];
    __shared__ unsigned int s_chunk, s_k2;
    int t = threadIdx.x;
    const unsigned int k1 = g_k1;
    unsigned int s = g_csum2[1023 - t];
    unsigned int incl = block_incl_scan(s, sh);
    unsigned int excl = incl - s;
    if (excl < k1 && k1 <= incl) { s_chunk = 1023 - t; s_k2 = k1 - excl; }
    __syncthreads();
    const unsigned int a = s_chunk;
    const unsigned int k2 = s_k2;
    unsigned int bin = a * 1024 + 1023 - t;
    unsigned int cb = g_hist2[bin];
    __syncthreads();
    unsigned int incl2 = block_incl_scan(cb, sh);
    unsigned int excl2 = incl2 - cb;
    if (excl2 < k2 && k2 <= incl2) {
        g_T = (g_prefix12 << 20) | bin;
        g_r = k2 - excl2;
    }
}

// ---------------------------------------------------------------------------
// ties among candidates, then cutoff = r-th smallest tie index
// ---------------------------------------------------------------------------
__global__ void tie_collect_k() {
    const unsigned int T = g_T;
    unsigned int m = g_cand_cnt;
    if (m > CAND_CAP) m = CAND_CAP;
    const unsigned int stride = gridDim.x * blockDim.x;
    for (unsigned int i = blockIdx.x * blockDim.x + threadIdx.x; i < m; i += stride) {
        if (g_cand_key[i] == T) {
            unsigned int p = atomicAdd(&g_tie_cnt, 1u);
            if (p < TIE_CAP) g_tie_idx[p] = g_cand_idx[i];
        }
    }
}

__global__ void cutoff_k(int n) {
    __shared__ int s_cnt;
    unsigned int m = g_tie_cnt;
    if (m > TIE_CAP) m = TIE_CAP;
    const unsigned int r = g_r;
    if (r == 0 || m == 0) { if (threadIdx.x == 0) g_cutoff = -1; return; }
    int lo = 0, hi = n - 1;
    while (lo < hi) {
        int mid = lo + (hi - lo) / 2;
        if (threadIdx.x == 0) s_cnt = 0;
        __syncthreads();
        int c = 0;
        for (unsigned int j = threadIdx.x; j < m; j += blockDim.x)
            if (g_tie_idx[j] <= mid) c++;
        if (c) atomicAdd(&s_cnt, c);
        __syncthreads();
        if (s_cnt >= (int)r) hi = mid; else lo = mid + 1;
        __syncthreads();
    }
    if (threadIdx.x == 0) g_cutoff = lo;
}

// ---------------------------------------------------------------------------
// fixup2: included candidates (key > T, or == T with idx <= cutoff) get the
// exact m=1 gumbel result.
// ---------------------------------------------------------------------------
__global__ void __launch_bounds__(256) fixup2_k(
        const float* __restrict__ u2,
        const int* __restrict__ training,
        float* __restrict__ out) {
    const unsigned int T = g_T;
    const int cutoff = g_cutoff;
    const int tr = *training;
    unsigned int m = g_cand_cnt;
    if (m > CAND_CAP) m = CAND_CAP;
    const unsigned int stride = gridDim.x * blockDim.x;
    for (unsigned int i = blockIdx.x * blockDim.x + threadIdx.x; i < m; i += stride) {
        unsigned int key = g_cand_key[i];
        if (key > T || (key == T && g_cand_idx[i] <= cutoff)) {
            int idx = g_cand_idx[i];
            float v = 1.0f;
            if (tr) {
                float2 uu = __ldg((const float2*)u2 + idx);
                float a0 = -logf(uu.x + EPSF) + EPSF;
                float a1 = -logf(uu.y + EPSF) + EPSF;
                v = (a1 < EULER_F * a0) ? 1.0f : 0.0f;
            }
            out[idx] = v;
        }
    }
}

// ---------------------------------------------------------------------------
extern "C" void kernel_launch(void* const* d_in, const int* in_sizes, int n_in,
                              void* d_out, int out_size) {
    const float* mask_logits = (const float*)d_in[0];
    const float* u1          = (const float*)d_in[1];
    const float* u2          = (const float*)d_in[2];
    const int*   kp          = (const int*)d_in[3];
    const int*   training    = (const int*)d_in[4];
    float* out = (float*)d_out;

    const int n  = in_sizes[0];
    const int n4 = n / 4;
    const int n8 = n / 8;

    reset_k<<<1, 1024>>>();
    score16_k<<<2048, 256>>>(mask_logits, u1, training, n4);
    select1_k<<<1, 1024>>>(kp);
    finalcand_k<<<2048, 256>>>(u2, mask_logits, u1, training, out, n8);
    chunksum2_k<<<1024, 256>>>();
    select2_k<<<1, 1024>>>();
    tie_collect_k<<<256, 256>>>();
    cutoff_k<<<1, 1024>>>(n);
    fixup2_k<<<1024, 256>>>(u2, training, out);
}

// round 15
// speedup vs baseline: 1.1754x; 1.1754x over previous
#include <cuda_runtime.h>
#include <cuda_bf16.h>
#include <stdint.h>

// ============================================================================
// GumbelTopK R15: R13 fused structure (keys32) + candidate-list radix select.
//  reset:    zero hist1/histA/histB/counters (1 tiny block)
//  A:        score -> keys32 (64MB W) + 12-bit smem hist         [192MB]
//  select1:  12-bit bin holding rank k
//  finalcand: keys32 + u2 -> out; in-bin (~2.7%) -> histA(bits 19:10)
//            + candidate {key,idx} staging                       [256MB]
//  selectA:  10-bit chunk holding rank k1 (over candidates)
//  histB:    candidates in chunk -> histB(bits 9:0)              [3.6MB]
//  selectB:  exact threshold T + rank r
//  tie/cutoff: key==T ties -> index cutoff
//  fixup2:   rewrite included candidates with exact gumbel       [small]
// m=1 gumbel: a1 < e*a0 (R12/13-validated exact); m=0: u1 > u0.
// ============================================================================

#define N_MAX    (1u << 24)      // 4096*4096
#define H1_BINS  4096
#define CAND_CAP (1u << 22)
#define TIE_CAP  (1u << 20)
#define CCAP     2048
#define EPSF     1e-8f
#define EULER_F  2.7182818284590452f

__device__ unsigned int g_keys[N_MAX];
__device__ unsigned int g_cand_key[CAND_CAP];
__device__ int          g_cand_idx[CAND_CAP];
__device__ int          g_tie_idx[TIE_CAP];
__device__ unsigned int g_hist1[H1_BINS];
__device__ unsigned int g_histA[1024];
__device__ unsigned int g_histB[1024];
__device__ unsigned int g_cand_cnt;
__device__ unsigned int g_tie_cnt;
__device__ unsigned int g_prefix12;
__device__ unsigned int g_k1;
__device__ unsigned int g_chunkA;
__device__ unsigned int g_k2;
__device__ unsigned int g_T;
__device__ unsigned int g_r;
__device__ int          g_cutoff;

__device__ __forceinline__ float gum(float u) {
    return -logf(-logf(u + EPSF) + EPSF);
}

__device__ __forceinline__ unsigned int f2key(float f) {
    unsigned int b = __float_as_uint(f);
    return (b & 0x80000000u) ? ~b : (b | 0x80000000u);
}

// ---------------------------------------------------------------------------
__global__ void reset_k() {
    for (int i = threadIdx.x; i < H1_BINS; i += blockDim.x) g_hist1[i] = 0;
    if (threadIdx.x < 1024) { g_histA[threadIdx.x] = 0; g_histB[threadIdx.x] = 0; }
    if (threadIdx.x == 0) { g_cand_cnt = 0; g_tie_cnt = 0; }
}

// ---------------------------------------------------------------------------
// pass A: score + keys32 store + 12-bit histogram (2-way replicated smem).
// ---------------------------------------------------------------------------
__global__ void __launch_bounds__(256) score_hist_k(
        const float* __restrict__ logits,
        const float* __restrict__ u1,
        const int* __restrict__ training, int n4) {
    __shared__ unsigned int sh[2 * H1_BINS];     // 32 KB
    for (int i = threadIdx.x; i < 2 * H1_BINS; i += blockDim.x) sh[i] = 0;
    __syncthreads();
    unsigned int* mysh = sh + ((threadIdx.x >> 5) & 1) * H1_BINS;
    const int tr = *training;
    const int stride = gridDim.x * blockDim.x;
    int i = blockIdx.x * blockDim.x + threadIdx.x;
    for (; i + stride < n4; i += 2 * stride) {
        float4 l0 = __ldcs((const float4*)logits + i);
        float4 u0 = __ldcs((const float4*)u1 + i);
        float4 l1 = __ldcs((const float4*)logits + i + stride);
        float4 u1v = __ldcs((const float4*)u1 + i + stride);
        uint4 k0, k1;
        k0.x = f2key(tr ? (l0.x + gum(u0.x)) : l0.x);
        k0.y = f2key(tr ? (l0.y + gum(u0.y)) : l0.y);
        k0.z = f2key(tr ? (l0.z + gum(u0.z)) : l0.z);
        k0.w = f2key(tr ? (l0.w + gum(u0.w)) : l0.w);
        k1.x = f2key(tr ? (l1.x + gum(u1v.x)) : l1.x);
        k1.y = f2key(tr ? (l1.y + gum(u1v.y)) : l1.y);
        k1.z = f2key(tr ? (l1.z + gum(u1v.z)) : l1.z);
        k1.w = f2key(tr ? (l1.w + gum(u1v.w)) : l1.w);
        ((uint4*)g_keys)[i] = k0;
        ((uint4*)g_keys)[i + stride] = k1;
        atomicAdd(&mysh[k0.x >> 20], 1u);
        atomicAdd(&mysh[k0.y >> 20], 1u);
        atomicAdd(&mysh[k0.z >> 20], 1u);
        atomicAdd(&mysh[k0.w >> 20], 1u);
        atomicAdd(&mysh[k1.x >> 20], 1u);
        atomicAdd(&mysh[k1.y >> 20], 1u);
        atomicAdd(&mysh[k1.z >> 20], 1u);
        atomicAdd(&mysh[k1.w >> 20], 1u);
    }
    for (; i < n4; i += stride) {
        float4 l = __ldcs((const float4*)logits + i);
        float4 u = __ldcs((const float4*)u1 + i);
        uint4 kk;
        kk.x = f2key(tr ? (l.x + gum(u.x)) : l.x);
        kk.y = f2key(tr ? (l.y + gum(u.y)) : l.y);
        kk.z = f2key(tr ? (l.z + gum(u.z)) : l.z);
        kk.w = f2key(tr ? (l.w + gum(u.w)) : l.w);
        ((uint4*)g_keys)[i] = kk;
        atomicAdd(&mysh[kk.x >> 20], 1u);
        atomicAdd(&mysh[kk.y >> 20], 1u);
        atomicAdd(&mysh[kk.z >> 20], 1u);
        atomicAdd(&mysh[kk.w >> 20], 1u);
    }
    __syncthreads();
    for (int b = threadIdx.x; b < H1_BINS; b += blockDim.x) {
        unsigned int c = sh[b] + sh[b + H1_BINS];
        if (c) atomicAdd(&g_hist1[b], c);
    }
}

// ---------------------------------------------------------------------------
__device__ __forceinline__ unsigned int block_incl_scan(unsigned int v, unsigned int* sh) {
    int t = threadIdx.x;
    sh[t] = v;
    __syncthreads();
    for (int off = 1; off < blockDim.x; off <<= 1) {
        unsigned int add = (t >= off) ? sh[t - off] : 0u;
        __syncthreads();
        sh[t] += add;
        __syncthreads();
    }
    return sh[t];
}

// select level 1: 12-bit bin holding rank-k (descending)
__global__ void select1_k(const int* __restrict__ kp) {
    __shared__ unsigned int sh[1024];
    const unsigned int k = (unsigned int)(*kp);
    int t = threadIdx.x;
    unsigned int c[4], s = 0;
#pragma unroll
    for (int j = 0; j < 4; j++) { c[j] = g_hist1[4095 - (4 * t + j)]; s += c[j]; }
    unsigned int incl = block_incl_scan(s, sh);
    unsigned int excl = incl - s;
    if (excl < k && k <= incl) {
        unsigned int cum = excl;
#pragma unroll
        for (int j = 0; j < 4; j++) {
            if (cum + c[j] >= k) { g_prefix12 = 4095 - (4 * t + j); g_k1 = k - cum; break; }
            cum += c[j];
        }
    }
}

// ---------------------------------------------------------------------------
// finalcand: fused output + candidate collection.
//  top12 > pfx -> mask 1;  < pfx -> mask 0;
//  == pfx -> provisional 0, histA(bits 19:10) atomic + staged candidate.
// ---------------------------------------------------------------------------
__device__ __forceinline__ float fc_elem(
        unsigned int key, int idx, float u0, float u1,
        unsigned int pfx, int tr,
        uint2* s_buf, int* s_cnt) {
    unsigned int top = key >> 20;
    unsigned int m = (top > pfx) ? 1u : 0u;
    if (top == pfx) {
        atomicAdd(&g_histA[(key >> 10) & 0x3FFu], 1u);
        int q = atomicAdd(s_cnt, 1);
        if (q < CCAP) s_buf[q] = make_uint2(key, (unsigned int)idx);
    }
    if (!tr) return m ? 1.0f : 0.0f;
    if (m) {
        float a0 = -logf(u0 + EPSF) + EPSF;
        float a1 = -logf(u1 + EPSF) + EPSF;
        return (a1 < EULER_F * a0) ? 1.0f : 0.0f;
    }
    return (u1 > u0) ? 1.0f : 0.0f;
}

__global__ void __launch_bounds__(256) finalcand_k(
        const float* __restrict__ u2,
        const int* __restrict__ training,
        float* __restrict__ out, int n4) {
    __shared__ uint2 s_buf[CCAP];    // 16 KB
    __shared__ int s_cnt;
    __shared__ unsigned int s_base;
    if (threadIdx.x == 0) s_cnt = 0;
    __syncthreads();
    const unsigned int pfx = g_prefix12;
    const int tr = *training;
    const int stride = gridDim.x * blockDim.x;
    int i = blockIdx.x * blockDim.x + threadIdx.x;
    for (; i + stride < n4; i += 2 * stride) {
        uint4 k0 = __ldcs((const uint4*)g_keys + i);
        float4 a0 = __ldcs((const float4*)u2 + 2 * i);
        float4 b0 = __ldcs((const float4*)u2 + 2 * i + 1);
        uint4 k1 = __ldcs((const uint4*)g_keys + i + stride);
        float4 a1 = __ldcs((const float4*)u2 + 2 * (i + stride));
        float4 b1 = __ldcs((const float4*)u2 + 2 * (i + stride) + 1);
        float4 o0, o1;
        o0.x = fc_elem(k0.x, 4 * i + 0, a0.x, a0.y, pfx, tr, s_buf, &s_cnt);
        o0.y = fc_elem(k0.y, 4 * i + 1, a0.z, a0.w, pfx, tr, s_buf, &s_cnt);
        o0.z = fc_elem(k0.z, 4 * i + 2, b0.x, b0.y, pfx, tr, s_buf, &s_cnt);
        o0.w = fc_elem(k0.w, 4 * i + 3, b0.z, b0.w, pfx, tr, s_buf, &s_cnt);
        int j = i + stride;
        o1.x = fc_elem(k1.x, 4 * j + 0, a1.x, a1.y, pfx, tr, s_buf, &s_cnt);
        o1.y = fc_elem(k1.y, 4 * j + 1, a1.z, a1.w, pfx, tr, s_buf, &s_cnt);
        o1.z = fc_elem(k1.z, 4 * j + 2, b1.x, b1.y, pfx, tr, s_buf, &s_cnt);
        o1.w = fc_elem(k1.w, 4 * j + 3, b1.z, b1.w, pfx, tr, s_buf, &s_cnt);
        __stcs((float4*)out + i, o0);
        __stcs((float4*)out + j, o1);
    }
    for (; i < n4; i += stride) {
        uint4 kk = __ldcs((const uint4*)g_keys + i);
        float4 a = __ldcs((const float4*)u2 + 2 * i);
        float4 b = __ldcs((const float4*)u2 + 2 * i + 1);
        float4 o;
        o.x = fc_elem(kk.x, 4 * i + 0, a.x, a.y, pfx, tr, s_buf, &s_cnt);
        o.y = fc_elem(kk.y, 4 * i + 1, a.z, a.w, pfx, tr, s_buf, &s_cnt);
        o.z = fc_elem(kk.z, 4 * i + 2, b.x, b.y, pfx, tr, s_buf, &s_cnt);
        o.w = fc_elem(kk.w, 4 * i + 3, b.z, b.w, pfx, tr, s_buf, &s_cnt);
        __stcs((float4*)out + i, o);
    }
    __syncthreads();
    int cnt = s_cnt;
    if (cnt > CCAP) cnt = CCAP;
    if (threadIdx.x == 0) s_base = atomicAdd(&g_cand_cnt, (unsigned int)cnt);
    __syncthreads();
    unsigned int base = s_base;
    for (int t = threadIdx.x; t < cnt; t += blockDim.x) {
        unsigned int p = base + t;
        if (p < CAND_CAP) {
            g_cand_key[p] = s_buf[t].x;
            g_cand_idx[p] = (int)s_buf[t].y;
        }
    }
}

// ---------------------------------------------------------------------------
// selectA: 10-bit chunk (bits 19:10 of low20) holding rank k1 (descending)
// ---------------------------------------------------------------------------
__global__ void selectA_k() {
    __shared__ unsigned int sh[1024];
    int t = threadIdx.x;
    const unsigned int k1 = g_k1;
    unsigned int bin = 1023 - t;
    unsigned int c = g_histA[bin];
    unsigned int incl = block_incl_scan(c, sh);
    unsigned int excl = incl - c;
    if (excl < k1 && k1 <= incl) {
        g_chunkA = bin;
        g_k2 = k1 - excl;
    }
}

// ---------------------------------------------------------------------------
// histB: candidates in selected chunk -> 10-bit histogram of bits 9:0
// ---------------------------------------------------------------------------
__global__ void __launch_bounds__(256) histB_k() {
    const unsigned int chunk = g_chunkA;
    unsigned int m = g_cand_cnt;
    if (m > CAND_CAP) m = CAND_CAP;
    const unsigned int stride = gridDim.x * blockDim.x;
    for (unsigned int i = blockIdx.x * blockDim.x + threadIdx.x; i < m; i += stride) {
        unsigned int key = g_cand_key[i];
        if (((key >> 10) & 0x3FFu) == chunk)
            atomicAdd(&g_histB[key & 0x3FFu], 1u);
    }
}

// selectB: exact threshold T + rank r
__global__ void selectB_k() {
    __shared__ unsigned int sh[1024];
    int t = threadIdx.x;
    const unsigned int k2 = g_k2;
    unsigned int bin = 1023 - t;
    unsigned int c = g_histB[bin];
    unsigned int incl = block_incl_scan(c, sh);
    unsigned int excl = incl - c;
    if (excl < k2 && k2 <= incl) {
        g_T = (g_prefix12 << 20) | (g_chunkA << 10) | bin;
        g_r = k2 - excl;
    }
}

// ---------------------------------------------------------------------------
// ties among candidates, then cutoff = r-th smallest tie index
// ---------------------------------------------------------------------------
__global__ void tie_collect_k() {
    const unsigned int T = g_T;
    unsigned int m = g_cand_cnt;
    if (m > CAND_CAP) m = CAND_CAP;
    const unsigned int stride = gridDim.x * blockDim.x;
    for (unsigned int i = blockIdx.x * blockDim.x + threadIdx.x; i < m; i += stride) {
        if (g_cand_key[i] == T) {
            unsigned int p = atomicAdd(&g_tie_cnt, 1u);
            if (p < TIE_CAP) g_tie_idx[p] = g_cand_idx[i];
        }
    }
}

__global__ void cutoff_k(int n) {
    __shared__ int s_cnt;
    unsigned int m = g_tie_cnt;
    if (m > TIE_CAP) m = TIE_CAP;
    const unsigned int r = g_r;
    if (r == 0 || m == 0) { if (threadIdx.x == 0) g_cutoff = -1; return; }
    int lo = 0, hi = n - 1;
    while (lo < hi) {
        int mid = lo + (hi - lo) / 2;
        if (threadIdx.x == 0) s_cnt = 0;
        __syncthreads();
        int c = 0;
        for (unsigned int j = threadIdx.x; j < m; j += blockDim.x)
            if (g_tie_idx[j] <= mid) c++;
        if (c) atomicAdd(&s_cnt, c);
        __syncthreads();
        if (s_cnt >= (int)r) hi = mid; else lo = mid + 1;
        __syncthreads();
    }
    if (threadIdx.x == 0) g_cutoff = lo;
}

// ---------------------------------------------------------------------------
// fixup2: included candidates (key > T, or == T with idx <= cutoff) get the
// exact m=1 gumbel result.
// ---------------------------------------------------------------------------
__global__ void __launch_bounds__(256) fixup2_k(
        const float* __restrict__ u2,
        const int* __restrict__ training,
        float* __restrict__ out) {
    const unsigned int T = g_T;
    const int cutoff = g_cutoff;
    const int tr = *training;
    unsigned int m = g_cand_cnt;
    if (m > CAND_CAP) m = CAND_CAP;
    const unsigned int stride = gridDim.x * blockDim.x;
    for (unsigned int i = blockIdx.x * blockDim.x + threadIdx.x; i < m; i += stride) {
        unsigned int key = g_cand_key[i];
        if (key > T || (key == T && g_cand_idx[i] <= cutoff)) {
            int idx = g_cand_idx[i];
            float v = 1.0f;
            if (tr) {
                float2 uu = __ldg((const float2*)u2 + idx);
                float a0 = -logf(uu.x + EPSF) + EPSF;
                float a1 = -logf(uu.y + EPSF) + EPSF;
                v = (a1 < EULER_F * a0) ? 1.0f : 0.0f;
            }
            out[idx] = v;
        }
    }
}

// ---------------------------------------------------------------------------
extern "C" void kernel_launch(void* const* d_in, const int* in_sizes, int n_in,
                              void* d_out, int out_size) {
    const float* mask_logits = (const float*)d_in[0];
    const float* u1          = (const float*)d_in[1];
    const float* u2          = (const float*)d_in[2];
    const int*   kp          = (const int*)d_in[3];
    const int*   training    = (const int*)d_in[4];
    float* out = (float*)d_out;

    const int n  = in_sizes[0];
    const int n4 = n / 4;

    reset_k<<<1, 1024>>>();
    score_hist_k<<<2048, 256>>>(mask_logits, u1, training, n4);
    select1_k<<<1, 1024>>>(kp);
    finalcand_k<<<4096, 256>>>(u2, training, out, n4);
    selectA_k<<<1, 1024>>>();
    histB_k<<<512, 256>>>();
    selectB_k<<<1, 1024>>>();
    tie_collect_k<<<256, 256>>>();
    cutoff_k<<<1, 1024>>>(n);
    fixup2_k<<<1024, 256>>>(u2, training, out);
}

// round 16
// speedup vs baseline: 1.2031x; 1.0236x over previous
#include <cuda_runtime.h>
#include <cuda_bf16.h>
#include <stdint.h>

// ============================================================================
// GumbelTopK R16: R15 + reg-lean finalcand + compressed tail.
//  reset:    zero hist1/histA/histB/counters (1 tiny block)
//  A:        score -> keys32 (64MB W) + 12-bit smem hist         [192MB]
//  select1:  12-bit bin holding rank k
//  finalcand: keys32 + u2 -> out (single-step loop, range cmp);
//            in-bin -> histA(bits 19:10) + candidate staging     [256MB]
//  selectA/histB/selectB: candidate radix -> exact T, rank r
//  fixup2:   cand key>T -> write out; key==T -> push tie         [small]
//  tiecut:   1 block: cutoff over ties, write included ties      [tiny]
// m=1 gumbel: a1 < e*a0 (validated exact); m=0: u1 > u0.
// ============================================================================

#define N_MAX    (1u << 24)      // 4096*4096
#define H1_BINS  4096
#define CAND_CAP (1u << 22)
#define TIE_CAP  65536
#define CCAP     2048
#define EPSF     1e-8f
#define EULER_F  2.7182818284590452f

__device__ unsigned int g_keys[N_MAX];
__device__ unsigned int g_cand_key[CAND_CAP];
__device__ int          g_cand_idx[CAND_CAP];
__device__ int          g_tie_idx[TIE_CAP];
__device__ unsigned int g_hist1[H1_BINS];
__device__ unsigned int g_histA[1024];
__device__ unsigned int g_histB[1024];
__device__ unsigned int g_cand_cnt;
__device__ unsigned int g_tie_cnt;
__device__ unsigned int g_prefix12;
__device__ unsigned int g_k1;
__device__ unsigned int g_chunkA;
__device__ unsigned int g_k2;
__device__ unsigned int g_T;
__device__ unsigned int g_r;

__device__ __forceinline__ float gum(float u) {
    return -logf(-logf(u + EPSF) + EPSF);
}

__device__ __forceinline__ unsigned int f2key(float f) {
    unsigned int b = __float_as_uint(f);
    return (b & 0x80000000u) ? ~b : (b | 0x80000000u);
}

// ---------------------------------------------------------------------------
__global__ void reset_k() {
    for (int i = threadIdx.x; i < H1_BINS; i += blockDim.x) g_hist1[i] = 0;
    if (threadIdx.x < 1024) { g_histA[threadIdx.x] = 0; g_histB[threadIdx.x] = 0; }
    if (threadIdx.x == 0) { g_cand_cnt = 0; g_tie_cnt = 0; }
}

// ---------------------------------------------------------------------------
// pass A: score + keys32 store + 12-bit histogram (2-way replicated smem).
// ---------------------------------------------------------------------------
__global__ void __launch_bounds__(256) score_hist_k(
        const float* __restrict__ logits,
        const float* __restrict__ u1,
        const int* __restrict__ training, int n4) {
    __shared__ unsigned int sh[2 * H1_BINS];     // 32 KB
    for (int i = threadIdx.x; i < 2 * H1_BINS; i += blockDim.x) sh[i] = 0;
    __syncthreads();
    unsigned int* mysh = sh + ((threadIdx.x >> 5) & 1) * H1_BINS;
    const int tr = *training;
    const int stride = gridDim.x * blockDim.x;
    int i = blockIdx.x * blockDim.x + threadIdx.x;
    for (; i + stride < n4; i += 2 * stride) {
        float4 l0 = __ldcs((const float4*)logits + i);
        float4 u0 = __ldcs((const float4*)u1 + i);
        float4 l1 = __ldcs((const float4*)logits + i + stride);
        float4 u1v = __ldcs((const float4*)u1 + i + stride);
        uint4 k0, k1;
        k0.x = f2key(tr ? (l0.x + gum(u0.x)) : l0.x);
        k0.y = f2key(tr ? (l0.y + gum(u0.y)) : l0.y);
        k0.z = f2key(tr ? (l0.z + gum(u0.z)) : l0.z);
        k0.w = f2key(tr ? (l0.w + gum(u0.w)) : l0.w);
        k1.x = f2key(tr ? (l1.x + gum(u1v.x)) : l1.x);
        k1.y = f2key(tr ? (l1.y + gum(u1v.y)) : l1.y);
        k1.z = f2key(tr ? (l1.z + gum(u1v.z)) : l1.z);
        k1.w = f2key(tr ? (l1.w + gum(u1v.w)) : l1.w);
        ((uint4*)g_keys)[i] = k0;
        ((uint4*)g_keys)[i + stride] = k1;
        atomicAdd(&mysh[k0.x >> 20], 1u);
        atomicAdd(&mysh[k0.y >> 20], 1u);
        atomicAdd(&mysh[k0.z >> 20], 1u);
        atomicAdd(&mysh[k0.w >> 20], 1u);
        atomicAdd(&mysh[k1.x >> 20], 1u);
        atomicAdd(&mysh[k1.y >> 20], 1u);
        atomicAdd(&mysh[k1.z >> 20], 1u);
        atomicAdd(&mysh[k1.w >> 20], 1u);
    }
    for (; i < n4; i += stride) {
        float4 l = __ldcs((const float4*)logits + i);
        float4 u = __ldcs((const float4*)u1 + i);
        uint4 kk;
        kk.x = f2key(tr ? (l.x + gum(u.x)) : l.x);
        kk.y = f2key(tr ? (l.y + gum(u.y)) : l.y);
        kk.z = f2key(tr ? (l.z + gum(u.z)) : l.z);
        kk.w = f2key(tr ? (l.w + gum(u.w)) : l.w);
        ((uint4*)g_keys)[i] = kk;
        atomicAdd(&mysh[kk.x >> 20], 1u);
        atomicAdd(&mysh[kk.y >> 20], 1u);
        atomicAdd(&mysh[kk.z >> 20], 1u);
        atomicAdd(&mysh[kk.w >> 20], 1u);
    }
    __syncthreads();
    for (int b = threadIdx.x; b < H1_BINS; b += blockDim.x) {
        unsigned int c = sh[b] + sh[b + H1_BINS];
        if (c) atomicAdd(&g_hist1[b], c);
    }
}

// ---------------------------------------------------------------------------
__device__ __forceinline__ unsigned int block_incl_scan(unsigned int v, unsigned int* sh) {
    int t = threadIdx.x;
    sh[t] = v;
    __syncthreads();
    for (int off = 1; off < blockDim.x; off <<= 1) {
        unsigned int add = (t >= off) ? sh[t - off] : 0u;
        __syncthreads();
        sh[t] += add;
        __syncthreads();
    }
    return sh[t];
}

// select level 1: 12-bit bin holding rank-k (descending)
__global__ void select1_k(const int* __restrict__ kp) {
    __shared__ unsigned int sh[1024];
    const unsigned int k = (unsigned int)(*kp);
    int t = threadIdx.x;
    unsigned int c[4], s = 0;
#pragma unroll
    for (int j = 0; j < 4; j++) { c[j] = g_hist1[4095 - (4 * t + j)]; s += c[j]; }
    unsigned int incl = block_incl_scan(s, sh);
    unsigned int excl = incl - s;
    if (excl < k && k <= incl) {
        unsigned int cum = excl;
#pragma unroll
        for (int j = 0; j < 4; j++) {
            if (cum + c[j] >= k) { g_prefix12 = 4095 - (4 * t + j); g_k1 = k - cum; break; }
            cum += c[j];
        }
    }
}

// ---------------------------------------------------------------------------
// finalcand: fused output + candidate collection. Reg-lean single-step loop.
//  key >= hi          -> mask 1
//  key - lo < 2^20    -> in-bin: provisional 0, histA atomic + staging
//  else               -> mask 0
// ---------------------------------------------------------------------------
__device__ __forceinline__ float fc_elem(
        unsigned int key, int idx, float u0, float u1,
        unsigned int lo, unsigned int hi, int tr,
        uint2* s_buf, int* s_cnt) {
    bool m = key >= hi;
    if (key - lo < 0x100000u) {          // lo <= key < hi
        atomicAdd(&g_histA[(key >> 10) & 0x3FFu], 1u);
        int q = atomicAdd(s_cnt, 1);
        if (q < CCAP) s_buf[q] = make_uint2(key, (unsigned int)idx);
    }
    if (!tr) return m ? 1.0f : 0.0f;
    if (m) {
        float a0 = -logf(u0 + EPSF) + EPSF;
        float a1 = -logf(u1 + EPSF) + EPSF;
        return (a1 < EULER_F * a0) ? 1.0f : 0.0f;
    }
    return (u1 > u0) ? 1.0f : 0.0f;
}

__global__ void __launch_bounds__(256) finalcand_k(
        const float* __restrict__ u2,
        const int* __restrict__ training,
        float* __restrict__ out, int n4) {
    __shared__ uint2 s_buf[CCAP];    // 16 KB
    __shared__ int s_cnt;
    __shared__ unsigned int s_base;
    if (threadIdx.x == 0) s_cnt = 0;
    __syncthreads();
    const unsigned int lo = g_prefix12 << 20;
    const unsigned int hi = lo + 0x100000u;
    const int tr = *training;
    const int stride = gridDim.x * blockDim.x;
    for (int i = blockIdx.x * blockDim.x + threadIdx.x; i < n4; i += stride) {
        uint4 kk = __ldcs((const uint4*)g_keys + i);
        float4 a = __ldcs((const float4*)u2 + 2 * i);
        float4 b = __ldcs((const float4*)u2 + 2 * i + 1);
        float4 o;
        o.x = fc_elem(kk.x, 4 * i + 0, a.x, a.y, lo, hi, tr, s_buf, &s_cnt);
        o.y = fc_elem(kk.y, 4 * i + 1, a.z, a.w, lo, hi, tr, s_buf, &s_cnt);
        o.z = fc_elem(kk.z, 4 * i + 2, b.x, b.y, lo, hi, tr, s_buf, &s_cnt);
        o.w = fc_elem(kk.w, 4 * i + 3, b.z, b.w, lo, hi, tr, s_buf, &s_cnt);
        __stcs((float4*)out + i, o);
    }
    __syncthreads();
    int cnt = s_cnt;
    if (cnt > CCAP) cnt = CCAP;
    if (threadIdx.x == 0) s_base = atomicAdd(&g_cand_cnt, (unsigned int)cnt);
    __syncthreads();
    unsigned int base = s_base;
    for (int t = threadIdx.x; t < cnt; t += blockDim.x) {
        unsigned int p = base + t;
        if (p < CAND_CAP) {
            g_cand_key[p] = s_buf[t].x;
            g_cand_idx[p] = (int)s_buf[t].y;
        }
    }
}

// ---------------------------------------------------------------------------
// selectA: 10-bit chunk (bits 19:10) holding rank k1 (descending)
// ---------------------------------------------------------------------------
__global__ void selectA_k() {
    __shared__ unsigned int sh[1024];
    int t = threadIdx.x;
    const unsigned int k1 = g_k1;
    unsigned int bin = 1023 - t;
    unsigned int c = g_histA[bin];
    unsigned int incl = block_incl_scan(c, sh);
    unsigned int excl = incl - c;
    if (excl < k1 && k1 <= incl) {
        g_chunkA = bin;
        g_k2 = k1 - excl;
    }
}

// histB: candidates in selected chunk -> 10-bit histogram of bits 9:0
__global__ void __launch_bounds__(256) histB_k() {
    const unsigned int chunk = g_chunkA;
    unsigned int m = g_cand_cnt;
    if (m > CAND_CAP) m = CAND_CAP;
    const unsigned int stride = gridDim.x * blockDim.x;
    for (unsigned int i = blockIdx.x * blockDim.x + threadIdx.x; i < m; i += stride) {
        unsigned int key = g_cand_key[i];
        if (((key >> 10) & 0x3FFu) == chunk)
            atomicAdd(&g_histB[key & 0x3FFu], 1u);
    }
}

// selectB: exact threshold T + rank r
__global__ void selectB_k() {
    __shared__ unsigned int sh[1024];
    int t = threadIdx.x;
    const unsigned int k2 = g_k2;
    unsigned int bin = 1023 - t;
    unsigned int c = g_histB[bin];
    unsigned int incl = block_incl_scan(c, sh);
    unsigned int excl = incl - c;
    if (excl < k2 && k2 <= incl) {
        g_T = (g_prefix12 << 20) | (g_chunkA << 10) | bin;
        g_r = k2 - excl;
    }
}

// ---------------------------------------------------------------------------
// fixup2: cand key > T -> write exact m=1 result; key == T -> push tie idx.
// ---------------------------------------------------------------------------
__global__ void __launch_bounds__(256) fixup2_k(
        const float* __restrict__ u2,
        const int* __restrict__ training,
        float* __restrict__ out) {
    const unsigned int T = g_T;
    const int tr = *training;
    unsigned int m = g_cand_cnt;
    if (m > CAND_CAP) m = CAND_CAP;
    const unsigned int stride = gridDim.x * blockDim.x;
    for (unsigned int i = blockIdx.x * blockDim.x + threadIdx.x; i < m; i += stride) {
        unsigned int key = g_cand_key[i];
        if (key > T) {
            int idx = g_cand_idx[i];
            float v = 1.0f;
            if (tr) {
                float2 uu = __ldg((const float2*)u2 + idx);
                float a0 = -logf(uu.x + EPSF) + EPSF;
                float a1 = -logf(uu.y + EPSF) + EPSF;
                v = (a1 < EULER_F * a0) ? 1.0f : 0.0f;
            }
            out[idx] = v;
        } else if (key == T) {
            unsigned int p = atomicAdd(&g_tie_cnt, 1u);
            if (p < TIE_CAP) g_tie_idx[p] = g_cand_idx[i];
        }
    }
}

// ---------------------------------------------------------------------------
// tiecut: 1 block. cutoff = r-th smallest tie index; write included ties.
// ---------------------------------------------------------------------------
__global__ void tiecut_k(const float* __restrict__ u2,
                         const int* __restrict__ training,
                         float* __restrict__ out, int n) {
    __shared__ int s_cnt;
    unsigned int m = g_tie_cnt;
    if (m > TIE_CAP) m = TIE_CAP;
    const unsigned int r = g_r;
    const int tr = *training;
    if (r == 0 || m == 0) return;
    int lo = 0, hi = n - 1;
    while (lo < hi) {
        int mid = lo + (hi - lo) / 2;
        if (threadIdx.x == 0) s_cnt = 0;
        __syncthreads();
        int c = 0;
        for (unsigned int j = threadIdx.x; j < m; j += blockDim.x)
            if (g_tie_idx[j] <= mid) c++;
        if (c) atomicAdd(&s_cnt, c);
        __syncthreads();
        if (s_cnt >= (int)r) hi = mid; else lo = mid + 1;
        __syncthreads();
    }
    int cutoff = lo;
    for (unsigned int j = threadIdx.x; j < m; j += blockDim.x) {
        int idx = g_tie_idx[j];
        if (idx <= cutoff) {
            float v = 1.0f;
            if (tr) {
                float2 uu = __ldg((const float2*)u2 + idx);
                float a0 = -logf(uu.x + EPSF) + EPSF;
                float a1 = -logf(uu.y + EPSF) + EPSF;
                v = (a1 < EULER_F * a0) ? 1.0f : 0.0f;
            }
            out[idx] = v;
        }
    }
}

// ---------------------------------------------------------------------------
extern "C" void kernel_launch(void* const* d_in, const int* in_sizes, int n_in,
                              void* d_out, int out_size) {
    const float* mask_logits = (const float*)d_in[0];
    const float* u1          = (const float*)d_in[1];
    const float* u2          = (const float*)d_in[2];
    const int*   kp          = (const int*)d_in[3];
    const int*   training    = (const int*)d_in[4];
    float* out = (float*)d_out;

    const int n  = in_sizes[0];
    const int n4 = n / 4;

    reset_k<<<1, 1024>>>();
    score_hist_k<<<2048, 256>>>(mask_logits, u1, training, n4);
    select1_k<<<1, 1024>>>(kp);
    finalcand_k<<<4096, 256>>>(u2, training, out, n4);
    selectA_k<<<1, 1024>>>();
    histB_k<<<512, 256>>>();
    selectB_k<<<1, 1024>>>();
    fixup2_k<<<512, 256>>>(u2, training, out);
    tiecut_k<<<1, 1024>>>(u2, training, out, n);
}